// round 14
// baseline (speedup 1.0000x reference)
#include <cuda_runtime.h>
#include <cstdint>

#define SZ 512
#define SLAB 64
#define NSLAB 8
#define NPLANES 256

// dynamic smem layout (bytes)
#define OFF_ROWP 0                     // float[4][64][33] row partials
#define OFF_COLP 33792                 // float[4][512]
#define OFF_PKM  41984                 // float[64]
#define OFF_PKA  42240
#define OFF_SNM  42496
#define OFF_SNA  42752
#define OFF_DAE  43008
#define OFF_BAND 43264                 // float[4][64]
#define OFF_CUTM 44288                 // float[64]
#define OFF_CUTA 44544
#define SMEM_TOTAL 44800

// cross-block scratch (allocation-free: __device__ globals)
__device__ float g_colsum[NPLANES][NSLAB][SZ];
__device__ float g_snapM[NPLANES][SZ];
__device__ float g_snapA[NPLANES][SZ];
__device__ float g_RT[NPLANES][SZ];
__device__ float g_PM[NPLANES][SZ];
__device__ float g_PA[NPLANES][SZ];
__device__ float g_DA[NPLANES][SZ];
__device__ unsigned int g_cnt[NPLANES];   // zero-init; self-reset each launch

__device__ __forceinline__ uint64_t pack2(float lo, float hi) {
    uint64_t d; asm("mov.b64 %0, {%1, %2};" : "=l"(d) : "f"(lo), "f"(hi)); return d;
}
__device__ __forceinline__ void unpack2(uint64_t d, float& lo, float& hi) {
    asm("mov.b64 {%0, %1}, %2;" : "=f"(lo), "=f"(hi) : "l"(d));
}
__device__ __forceinline__ uint64_t addf32x2(uint64_t a, uint64_t b) {
    uint64_t d; asm("add.rn.f32x2 %0, %1, %2;" : "=l"(d) : "l"(a), "l"(b)); return d;
}

__global__ __launch_bounds__(512, 2)
void slab_kernel(const float* __restrict__ x, float* __restrict__ out) {
    extern __shared__ char SB[];
    float* sRowPart = (float*)(SB + OFF_ROWP);   // [(band*64+row)*33 + lane]
    float* sColPart = (float*)(SB + OFF_COLP);   // [rowgroup*512 + col]
    float* sPkM     = (float*)(SB + OFF_PKM);
    float* sPkA     = (float*)(SB + OFF_PKA);
    float* sSnapM   = (float*)(SB + OFF_SNM);    // row-indexed
    float* sSnapA   = (float*)(SB + OFF_SNA);    // row-indexed
    float* sDA      = (float*)(SB + OFF_DAE);
    float* sBandRow = (float*)(SB + OFF_BAND);   // [band*64 + row]
    float* sCutM    = (float*)(SB + OFF_CUTM);
    float* sCutA    = (float*)(SB + OFF_CUTA);
    // last-block combine arrays alias the (dead-by-then) sRowPart region
    float* cA1  = (float*)(SB + 0);
    float* cA2  = (float*)(SB + 2048);
    float* cCT  = (float*)(SB + 4096);
    float* cRT  = (float*)(SB + 6144);
    float* cPM  = (float*)(SB + 8192);
    float* cPA  = (float*)(SB + 10240);
    float* cDAo = (float*)(SB + 12288);
    __shared__ bool amLast;

    const int blk = blockIdx.x;
    const int p = blk >> 3;                    // plane
    const int s = blk & 7;                     // 64-row slab
    const int sh = s & 1;
    const int sb = s >> 1;                     // main-cut column band
    const float* __restrict__ X = x + ((size_t)p * SZ + (size_t)s * SLAB) * SZ;

    const int tid  = threadIdx.x;
    const int w    = tid >> 5;
    const int lane = tid & 31;
    const int wr = w >> 2, wc = w & 3;         // 4 rowgroups(16) x 4 bands(128)
    const int c0  = wc * 128;
    const int lr0 = wr * 16;
    const bool mainRole = (wc == sb);
    const bool antiRole = (wc == 3 - sb);

    const float4* __restrict__ base =
        reinterpret_cast<const float4*>(X + (size_t)lr0 * SZ + c0) + lane;
    const int RS4 = SZ / 4;

    uint64_t acc01 = 0ull, acc23 = 0ull;

#pragma unroll
    for (int g = 0; g < 2; ++g) {
        const int lrg = lr0 + 8 * g;

        float4 v[8];
#pragma unroll
        for (int u = 0; u < 8; u++)
            v[u] = __ldcs(base + (8 * g + u) * RS4);

        float sv[8];
#pragma unroll
        for (int u = 0; u < 8; u++) {
            uint64_t h = addf32x2(pack2(v[u].x, v[u].y), pack2(v[u].z, v[u].w));
            float lo, hi; unpack2(h, lo, hi);
            sv[u] = lo + hi;
        }

        // store per-lane row partials (conflict-free)
        {
            float* rp = sRowPart + (wc * SLAB + lrg) * 33 + lane;
#pragma unroll
            for (int u = 0; u < 8; u++)
                rp[u * 33] = sv[u];
        }

        // role-warp scalars: cut pk, snapshots (acc read BEFORE that row's update) + acc update
#pragma unroll
        for (int u = 0; u < 8; u++) {
            const int lr = lrg + u;
            if (mainRole) {
                const int ls = 16 * sh + 4 * wr + 2 * g + (u >> 2);
                const int k = u & 3;                   // compile-time
                if (lane == ls) {
                    const float pkv = (k == 0) ? v[u].x
                                    : (k == 1) ? (v[u].x + v[u].y)
                                    : (k == 2) ? ((v[u].x + v[u].y) + v[u].z)
                                    : sv[u];
                    sPkM[lr] = pkv;
                    float lo, hi, sn;
                    if (k < 2) { unpack2(acc01, lo, hi); sn = (k == 0) ? lo : hi; }
                    else       { unpack2(acc23, lo, hi); sn = (k == 2) ? lo : hi; }
                    sSnapM[lr] = sn;
                }
            }
            if (antiRole) {
                const int lsA = ((127 - 64 * sh - lrg) >> 2) - (u >> 2);
                const int kA = 3 - (u & 3);            // compile-time
                if (lane == lsA) {
                    const float pkv = (kA == 3) ? sv[u]
                                    : (kA == 2) ? ((v[u].x + v[u].y) + v[u].z)
                                    : (kA == 1) ? (v[u].x + v[u].y)
                                    : v[u].x;
                    sPkA[lr] = pkv;
                    const float e = (kA == 0) ? v[u].x : (kA == 1) ? v[u].y
                                  : (kA == 2) ? v[u].z : v[u].w;
                    float lo, hi, sn;
                    if (kA < 2) { unpack2(acc01, lo, hi); sn = (kA == 0) ? lo : hi; }
                    else        { unpack2(acc23, lo, hi); sn = (kA == 2) ? lo : hi; }
                    sSnapA[lr] = sn;
                    sDA[lr] = e;
                }
            }
            acc01 = addf32x2(acc01, pack2(v[u].x, v[u].y));
            acc23 = addf32x2(acc23, pack2(v[u].z, v[u].w));
        }
    }

    {
        float a0, a1, a2, a3;
        unpack2(acc01, a0, a1);
        unpack2(acc23, a2, a3);
        *reinterpret_cast<float4*>(sColPart + wr * SZ + c0 + lane * 4) = make_float4(a0, a1, a2, a3);
    }
    __syncthreads();

    // ---- phase 2a: reduce row partials from smem (no shuffles) ----
    if (tid < 4 * SLAB) {
        const int band = tid >> 6;
        const int lr = tid & 63;
        const float* rp = sRowPart + (band * SLAB + lr) * 33;
        const int lsM = 16 * sh + (lr >> 2);
        const int lsA = (127 - 64 * sh - lr) >> 2;
        float full = 0.f, cutM = 0.f, cutA = 0.f;
#pragma unroll
        for (int k = 0; k < 32; ++k) {
            const float vv = rp[k];
            full += vv;
            if (k < lsM) cutM += vv;
            if (k < lsA) cutA += vv;
        }
        sBandRow[band * SLAB + lr] = full;
        if (band == sb)     sCutM[lr] = cutM + sPkM[lr];
        if (band == 3 - sb) sCutA[lr] = cutA + sPkA[lr];
    }
    // ---- slab combine: columns (independent of phase 2a) ----
    {
        const int c = tid;
        const float q0 = sColPart[0 * SZ + c], q1 = sColPart[1 * SZ + c],
                    q2 = sColPart[2 * SZ + c], q3 = sColPart[3 * SZ + c];
        g_colsum[p][s][c] = (q0 + q1) + (q2 + q3);

        if ((c >> 6) == s) {                        // col c is a main-diag row of this slab
            const int lr = c - SLAB * s;
            const int rg = lr >> 4;
            float sn = sSnapM[lr];
            if (rg > 0) sn += q0;
            if (rg > 1) sn += q1;
            if (rg > 2) sn += q2;
            g_snapM[p][c] = sn;
        }
        if (((SZ - 1 - c) >> 6) == s) {             // col c is an anti-diag col of this slab
            const int lr = (SZ - 1 - c) - SLAB * s;
            const int rg = lr >> 4;
            float sn = sSnapA[lr];
            if (rg > 0) sn += q0;
            if (rg > 1) sn += q1;
            if (rg > 2) sn += q2;
            g_snapA[p][c] = sn;
        }
    }
    __syncthreads();

    // ---- slab combine: rows ----
    if (tid < SLAB) {
        const int lr = tid;
        const int gr = SLAB * s + lr;
        const float b0 = sBandRow[0 * SLAB + lr], b1 = sBandRow[1 * SLAB + lr],
                    b2 = sBandRow[2 * SLAB + lr], b3 = sBandRow[3 * SLAB + lr];
        g_RT[p][gr] = (b0 + b1) + (b2 + b3);

        float pm = sCutM[lr];
        if (sb > 0) pm += b0;
        if (sb > 1) pm += b1;
        if (sb > 2) pm += b2;
        g_PM[p][gr] = pm;

        const int ab = 3 - sb;
        float pa = sCutA[lr];
        if (ab > 0) pa += b0;
        if (ab > 1) pa += b1;
        if (ab > 2) pa += b2;
        g_PA[p][gr] = pa;

        g_DA[p][gr] = sDA[lr];
    }

    // ---- last-block-per-plane fused combine ----
    __threadfence();
    __syncthreads();
    if (tid == 0) {
        const unsigned t = atomicAdd(&g_cnt[p], 1u);
        amLast = (t == NSLAB - 1u);
        if (amLast) g_cnt[p] = 0;
    }
    __syncthreads();
    if (!amLast) return;

    {
        const int i = tid;
        float q[NSLAB];
#pragma unroll
        for (int k = 0; k < NSLAB; k++) q[k] = g_colsum[p][k][i];
        float ct = 0.f;
#pragma unroll
        for (int k = 0; k < NSLAB; k++) ct += q[k];
        cCT[i] = ct;

        const int jm = i >> 6;
        float a1 = g_snapM[p][i];
#pragma unroll
        for (int k = 0; k < NSLAB - 1; k++) if (k < jm) a1 += q[k];
        cA1[i] = a1;

        const int ja = (SZ - 1 - i) >> 6;
        float a2 = g_snapA[p][i];
#pragma unroll
        for (int k = 0; k < NSLAB - 1; k++) if (k < ja) a2 += q[k];
        cA2[i] = a2;

        cRT[i] = g_RT[p][i]; cPM[i] = g_PM[p][i]; cPA[i] = g_PA[p][i]; cDAo[i] = g_DA[p][i];
    }
    __syncthreads();
    {
        const int i = tid;
        const int m = SZ - 1 - i;

        const float tl = cPM[i] + cA1[i];
        const float tr = cRT[i] - cPA[i] + cDAo[i] + cA2[m];
        const float bl = cPA[m] + cCT[i] - cA2[i] - cDAo[m];
        const float br = cRT[m] - cPM[m] + cCT[m] - cA1[m];

        const float inv = 1.0f / (float)(2 * i + 1);
        const int b  = p >> 3;
        const int ch = p & 7;
        float* __restrict__ o = out + ((size_t)(b * SZ + i)) * 32 + ch;
        o[0]  = tl * inv;
        o[8]  = tr * inv;
        o[16] = bl * inv;
        o[24] = br * inv;
    }
}

extern "C" void kernel_launch(void* const* d_in, const int* in_sizes, int n_in,
                              void* d_out, int out_size) {
    const float* x = (const float*)d_in[0];
    float* out = (float*)d_out;
    const int planes = in_sizes[0] / (SZ * SZ);   // 256
    static bool attrSet = false;
    if (!attrSet) {
        cudaFuncSetAttribute(slab_kernel, cudaFuncAttributeMaxDynamicSharedMemorySize, SMEM_TOTAL);
        attrSet = true;
    }
    slab_kernel<<<planes * NSLAB, 512, SMEM_TOTAL>>>(x, out);
}